// round 13
// baseline (speedup 1.0000x reference)
#include <cuda_runtime.h>
#include <cuda_fp16.h>
#include <cstdint>

#define NN   10000
#define DEG  32
#define FF   512
#define NCTA 296                    // 2 CTAs/SM x 148 SMs (<= residency, proven occ=2)
#define NTILE (79 * 16)             // 128x128 tiles covering 10000 x 2048

// ---------------- scratch (static device globals; no allocation) ----------
static __device__ float  g_Xp   [(size_t)NN * 2048];
static __device__ __half g_sageA[(size_t)NN * 1024];
static __device__ __half g_hA   [(size_t)NN * 512];
static __device__ __half g_hB   [(size_t)NN * 512];
static __device__ __half g_hs16 [(size_t)NN * 512];
static __device__ __half g_Wih1b[(size_t)2048 * 512];
static __device__ __half g_Whh1b[(size_t)2048 * 512];
static __device__ __half g_Wih2b[(size_t)2048 * 512];
static __device__ __half g_Whh2b[(size_t)2048 * 512];
static __device__ __half g_WbS  [(size_t)512 * 1024];
static __device__ float  g_bsum1[2048];
static __device__ float  g_bsum2[2048];
static __device__ float  g_c    [(size_t)NN * FF];
static __device__ unsigned g_ctr[64];   // grid-barrier counters (reset via memsetAsync)

__device__ __forceinline__ float sig_(float x) {
    return __fdividef(1.0f, 1.0f + __expf(-x));
}
__device__ __forceinline__ float tanh_(float x) {
    float e = __expf(-2.0f * fabsf(x));
    float t = __fdividef(1.0f - e, 1.0f + e);
    return copysignf(t, x);
}
__device__ __forceinline__ uint32_t smem_u32(const void* p) {
    uint32_t a;
    asm("{ .reg .u64 t; cvta.to.shared.u64 t, %1; cvt.u32.u64 %0, t; }" : "=r"(a) : "l"(p));
    return a;
}
__device__ __forceinline__ void cpa16(uint32_t saddr, const void* g, int ss) {
    asm volatile("cp.async.cg.shared.global [%0], [%1], 16, %2;"
                 :: "r"(saddr), "l"(g), "r"(ss) : "memory");
}
__device__ __forceinline__ void ldsm4(uint32_t* r, uint32_t addr) {
    asm volatile("ldmatrix.sync.aligned.m8n8.x4.shared.b16 {%0,%1,%2,%3}, [%4];"
                 : "=r"(r[0]), "=r"(r[1]), "=r"(r[2]), "=r"(r[3]) : "r"(addr));
}
__device__ __forceinline__ void mma16816(float* d, const uint32_t* a, const uint32_t* b) {
    asm volatile("mma.sync.aligned.m16n8k16.row.col.f32.f16.f16.f32 "
                 "{%0,%1,%2,%3}, {%4,%5,%6,%7}, {%8,%9}, {%0,%1,%2,%3};"
                 : "+f"(d[0]), "+f"(d[1]), "+f"(d[2]), "+f"(d[3])
                 : "r"(a[0]), "r"(a[1]), "r"(a[2]), "r"(a[3]), "r"(b[0]), "r"(b[1]));
}
__device__ __forceinline__ float ldcg(const float* p) {
    float v; asm volatile("ld.global.cg.f32 %0, [%1];" : "=f"(v) : "l"(p)); return v;
}
__device__ __forceinline__ void stcg(float* p, float v) {
    asm volatile("st.global.cg.f32 [%0], %1;" :: "l"(p), "f"(v) : "memory");
}

// geometry: block 128x128, 256 threads (8 warps: wm 0..1 x wn 0..3), warp 64x32
// stage = K=64 slab: A 128x64 + B 128x64, PAD 72 halfs/row
#define PAD      72
#define A_TILE_B 18432
#define B_TILE_B 18432
#define STAGE_B  36864
#define NSTAGE   3
#define SRC_B    512
#define SMEMB    (NSTAGE * STAGE_B + SRC_B)   // 111,104 (x2 CTAs = 222.2KB)

// ---------------------------------------------------------------------------
// Persistent LSTM chain: steps t=1..31 in ONE launch, grid-wide barrier/step.
// A = h(t-1) [NN,512] fp16 ping-pong; B = Whh fp16 [2048,512] interleaved rows.
// t<31: h(t) -> ping-pong fp16. t==31: fp16 -> hFin(+foff,fstride), fp32 -> f32out.
// ---------------------------------------------------------------------------
__global__ void __launch_bounds__(256, 2) lstm_chain_kernel(
    const __half* __restrict__ Whh, const float* __restrict__ Xp,
    const int* __restrict__ src, float* __restrict__ cbuf,
    __half* __restrict__ hA, __half* __restrict__ hB,
    __half* __restrict__ hFin, int fstride, int foff,
    float* __restrict__ f32out, int ctrBase)
{
    extern __shared__ __align__(16) char smem[];
    const uint32_t sbase = smem_u32(smem);
    int* const sSrc = (int*)(smem + NSTAGE * STAGE_B);
    const int tid  = threadIdx.x;
    const int warp = tid >> 5, lane = tid & 31;
    const int wn = warp & 3, wm = warp >> 2;

    const int rA = tid >> 3, seg8 = tid & 7;
    const uint32_t aL = (uint32_t)((lane & 15) * PAD + (lane >> 4) * 8) * 2;
    const uint32_t bL = (uint32_t)(((lane & 7) + ((lane >> 4) << 3)) * PAD
                                   + ((lane >> 3) & 1) * 8) * 2;
    const uint32_t aWm = (uint32_t)(wm * 64 * PAD) * 2;
    const uint32_t bWn = (uint32_t)(wn * 32 * PAD) * 2;

    #pragma unroll 1
    for (int t = 1; t <= 31; t++) {
        const __half* hin = (t & 1) ? hB : hA;
        __half* hout; int hstr, hof; float* f32o;
        if (t < 31) { hout = (t & 1) ? hA : hB; hstr = 512; hof = 0; f32o = nullptr; }
        else        { hout = hFin; hstr = fstride; hof = foff; f32o = f32out; }

        #pragma unroll 1
        for (int tile = blockIdx.x; tile < NTILE; tile += NCTA) {
            const int bm = tile % 79, bn = tile / 79;
            const int m0 = bm * 128, n0 = bn * 128;

            __syncthreads();                      // protect sSrc reuse
            if (tid < 128) {
                const int rr = m0 + tid;
                sSrc[tid] = (rr < NN) ? src[rr * DEG + t] : 0;
            }

            float accP[4][4][4];
            #pragma unroll
            for (int mi = 0; mi < 4; mi++)
                #pragma unroll
                for (int nj = 0; nj < 4; nj++)
                    #pragma unroll
                    for (int r = 0; r < 4; r++) accP[mi][nj][r] = 0.f;

            int aszv[4]; size_t aGv[4], bGv[4]; uint32_t tSmv[4];
            #pragma unroll
            for (int i = 0; i < 4; i++) {
                const int r = rA + i * 32;
                aszv[i] = (m0 + r < NN) ? 16 : 0;
                aGv[i]  = (size_t)((m0 + r < NN) ? (m0 + r) : 0) * 512 + seg8 * 8;
                bGv[i]  = (size_t)(n0 + r) * 512 + seg8 * 8;
                tSmv[i] = (uint32_t)(r * PAD + seg8 * 8) * 2;
            }

            auto issue = [&](int st, int buf) {
                const int kc = st << 6;
                const uint32_t s0 = sbase + buf * STAGE_B;
                #pragma unroll
                for (int i = 0; i < 4; i++)
                    cpa16(s0 + tSmv[i], hin + aGv[i] + kc, aszv[i]);
                #pragma unroll
                for (int i = 0; i < 4; i++)
                    cpa16(s0 + A_TILE_B + tSmv[i], Whh + bGv[i] + kc, 16);
                asm volatile("cp.async.commit_group;" ::: "memory");
            };

            issue(0, 0);
            issue(1, 1);
            int buf = 0;
            #pragma unroll 1
            for (int st = 0; st < 8; st++) {      // K = 512 = 8 x 64
                if (st < 7)
                    asm volatile("cp.async.wait_group 1;" ::: "memory");
                else
                    asm volatile("cp.async.wait_group 0;" ::: "memory");
                __syncthreads();
                if (st + 2 < 8) {
                    int nb = buf + 2; if (nb >= NSTAGE) nb -= NSTAGE;
                    issue(st + 2, nb);
                }
                const uint32_t s0 = sbase + buf * STAGE_B;
                #pragma unroll
                for (int ks = 0; ks < 4; ks++) {
                    uint32_t aH[4][4], bH[2][4];
                    #pragma unroll
                    for (int mi = 0; mi < 4; mi++)
                        ldsm4(aH[mi], s0 + aWm + aL + (uint32_t)(mi * 16 * PAD + ks * 16) * 2);
                    #pragma unroll
                    for (int njp = 0; njp < 2; njp++)
                        ldsm4(bH[njp], s0 + A_TILE_B + bWn + bL + (uint32_t)(njp * 16 * PAD + ks * 16) * 2);
                    #pragma unroll
                    for (int mi = 0; mi < 4; mi++)
                        #pragma unroll
                        for (int nj = 0; nj < 4; nj++)
                            mma16816(accP[mi][nj], aH[mi], &bH[nj >> 1][(nj & 1) * 2]);
                }
                buf++; if (buf >= NSTAGE) buf -= NSTAGE;
            }

            // ---- LSTM gate epilogue ----
            #pragma unroll
            for (int mi = 0; mi < 4; mi++)
                #pragma unroll
                for (int nj = 0; nj < 4; nj++) {
                    float v0 = accP[mi][nj][0];
                    float v1 = accP[mi][nj][1];
                    float v2 = accP[mi][nj][2];
                    float v3 = accP[mi][nj][3];
                    const float p0 = __shfl_xor_sync(0xffffffffu, v0, 1);
                    const float p1 = __shfl_xor_sync(0xffffffffu, v1, 1);
                    const float p2 = __shfl_xor_sync(0xffffffffu, v2, 1);
                    const float p3 = __shfl_xor_sync(0xffffffffu, v3, 1);
                    const int q = lane & 1;
                    const int rl = wm * 64 + mi * 16 + (lane >> 2) + (q << 3);
                    const int rowU = m0 + rl;
                    const int hc = ((n0 + wn * 32 + nj * 8) >> 2) + ((lane & 3) >> 1);
                    if (rowU < NN) {
                        float gi, gf, gg, go;
                        if (!q) { gi = v0; gf = v1; gg = p0; go = p1; }
                        else    { gi = p2; gf = p3; gg = v2; go = v3; }
                        const int s = sSrc[rl];
                        const float4 xv = *(const float4*)(Xp + (size_t)s * 2048 + 4 * hc);
                        gi += xv.x; gf += xv.y; gg += xv.z; go += xv.w;
                        float* cp = cbuf + (size_t)rowU * FF + hc;
                        const float cn = sig_(gf) * ldcg(cp) + sig_(gi) * tanh_(gg);
                        stcg(cp, cn);
                        const float hv = sig_(go) * tanh_(cn);
                        if (f32o) f32o[(size_t)rowU * FF + hc] = hv;
                        if (hout) hout[(size_t)rowU * hstr + hof + hc] = __float2half_rn(hv);
                    }
                }
        }

        // ---- grid-wide barrier for step t ----
        __syncthreads();
        if (tid == 0) {
            __threadfence();
            atomicAdd(&g_ctr[ctrBase + t], 1u);
            while (*(volatile unsigned*)&g_ctr[ctrBase + t] < (unsigned)NCTA)
                __nanosleep(64);
        }
        __syncthreads();
    }
}

// ---------------------------------------------------------------------------
// Regular GEMM (modes 0/2 only): proj and sage. Same tile as chain kernel.
// ---------------------------------------------------------------------------
__global__ void __launch_bounds__(256, 2) gemm_f16_kernel(
    const __half* __restrict__ A, int lda,
    const __half* __restrict__ B2, int K, int mode,
    const float* __restrict__ bias, float* __restrict__ XpOut,
    __half* __restrict__ hout, int hstride, int hoff)
{
    extern __shared__ __align__(16) char smem[];
    const uint32_t sbase = smem_u32(smem);
    const int tid  = threadIdx.x;
    const int warp = tid >> 5, lane = tid & 31;
    const int wn = warp & 3, wm = warp >> 2;
    const int m0 = blockIdx.x * 128, n0 = blockIdx.y * 128;
    const int nst = K >> 6;

    float accP[4][4][4];
    #pragma unroll
    for (int mi = 0; mi < 4; mi++)
        #pragma unroll
        for (int nj = 0; nj < 4; nj++)
            #pragma unroll
            for (int r = 0; r < 4; r++) accP[mi][nj][r] = 0.f;

    const int rA = tid >> 3, seg8 = tid & 7;
    int aszv[4]; size_t aGv[4], bGv[4]; uint32_t tSmv[4];
    #pragma unroll
    for (int i = 0; i < 4; i++) {
        const int r = rA + i * 32;
        aszv[i] = (m0 + r < NN) ? 16 : 0;
        aGv[i]  = (size_t)((m0 + r < NN) ? (m0 + r) : 0) * lda + seg8 * 8;
        bGv[i]  = (size_t)(n0 + r) * K + seg8 * 8;
        tSmv[i] = (uint32_t)(r * PAD + seg8 * 8) * 2;
    }
    const uint32_t aL = (uint32_t)((lane & 15) * PAD + (lane >> 4) * 8) * 2;
    const uint32_t bL = (uint32_t)(((lane & 7) + ((lane >> 4) << 3)) * PAD
                                   + ((lane >> 3) & 1) * 8) * 2;
    const uint32_t aWm = (uint32_t)(wm * 64 * PAD) * 2;
    const uint32_t bWn = (uint32_t)(wn * 32 * PAD) * 2;

    auto issue = [&](int st, int buf) {
        const int kc = st << 6;
        const uint32_t s0 = sbase + buf * STAGE_B;
        #pragma unroll
        for (int i = 0; i < 4; i++)
            cpa16(s0 + tSmv[i], A + aGv[i] + kc, aszv[i]);
        #pragma unroll
        for (int i = 0; i < 4; i++)
            cpa16(s0 + A_TILE_B + tSmv[i], B2 + bGv[i] + kc, 16);
        asm volatile("cp.async.commit_group;" ::: "memory");
    };

    issue(0, 0);
    if (nst > 1) issue(1, 1);
    int buf = 0;
    #pragma unroll 1
    for (int st = 0; st < nst; st++) {
        if (st + 1 < nst)
            asm volatile("cp.async.wait_group 1;" ::: "memory");
        else
            asm volatile("cp.async.wait_group 0;" ::: "memory");
        __syncthreads();
        if (st + 2 < nst) {
            int nb = buf + 2; if (nb >= NSTAGE) nb -= NSTAGE;
            issue(st + 2, nb);
        }
        const uint32_t s0 = sbase + buf * STAGE_B;
        #pragma unroll
        for (int ks = 0; ks < 4; ks++) {
            uint32_t aH[4][4], bH[2][4];
            #pragma unroll
            for (int mi = 0; mi < 4; mi++)
                ldsm4(aH[mi], s0 + aWm + aL + (uint32_t)(mi * 16 * PAD + ks * 16) * 2);
            #pragma unroll
            for (int njp = 0; njp < 2; njp++)
                ldsm4(bH[njp], s0 + A_TILE_B + bWn + bL + (uint32_t)(njp * 16 * PAD + ks * 16) * 2);
            #pragma unroll
            for (int mi = 0; mi < 4; mi++)
                #pragma unroll
                for (int nj = 0; nj < 4; nj++)
                    mma16816(accP[mi][nj], aH[mi], &bH[nj >> 1][(nj & 1) * 2]);
        }
        buf++; if (buf >= NSTAGE) buf -= NSTAGE;
    }

    #pragma unroll
    for (int mi = 0; mi < 4; mi++)
        #pragma unroll
        for (int nj = 0; nj < 4; nj++) {
            const int c0 = n0 + wn * 32 + nj * 8 + (lane & 3) * 2;
            const int rr = m0 + wm * 64 + mi * 16 + (lane >> 2);
            const float2 bs = make_float2(bias[c0], bias[c0 + 1]);
            float v0 = accP[mi][nj][0] + bs.x;
            float v1 = accP[mi][nj][1] + bs.y;
            float v2 = accP[mi][nj][2] + bs.x;
            float v3 = accP[mi][nj][3] + bs.y;
            if (mode == 0) {
                if (rr < NN)     *(float2*)(XpOut + (size_t)rr * 2048 + c0) = make_float2(v0, v1);
                if (rr + 8 < NN) *(float2*)(XpOut + (size_t)(rr + 8) * 2048 + c0) = make_float2(v2, v3);
            } else {
                if (rr < NN)
                    *(__half2*)(hout + (size_t)rr * hstride + hoff + c0) =
                        __halves2half2(__float2half_rn(v0), __float2half_rn(v1));
                if (rr + 8 < NN)
                    *(__half2*)(hout + (size_t)(rr + 8) * hstride + hoff + c0) =
                        __halves2half2(__float2half_rn(v2), __float2half_rn(v3));
            }
        }
}

// ---------------------------------------------------------------------------
__global__ void __launch_bounds__(256) conv_w_kernel(
    const float* __restrict__ W, const float* __restrict__ b1, const float* __restrict__ b2,
    __half* __restrict__ W2, float* __restrict__ bsum)
{
    const int idx = blockIdx.x * 256 + threadIdx.x;
    if (idx >= 2048 * 512) return;
    const int jp = idx >> 9, k = idx & 511;
    const int orig = (jp & 3) * 512 + (jp >> 2);
    W2[(size_t)jp * 512 + k] = __float2half_rn(W[(size_t)orig * 512 + k]);
    if (k == 0 && bsum) bsum[jp] = b1[orig] + b2[orig];
}

__global__ void __launch_bounds__(256) conv_w_sage_kernel(
    const float* __restrict__ Ws, const float* __restrict__ Wn,
    __half* __restrict__ W2)
{
    const int idx = blockIdx.x * 256 + threadIdx.x;
    if (idx >= 512 * 1024) return;
    const int j = idx >> 10, k = idx & 1023;
    const float w = (k < 512) ? Ws[(size_t)k * 512 + j] : Wn[(size_t)(k - 512) * 512 + j];
    W2[(size_t)j * 1024 + k] = __float2half_rn(w);
}

__global__ void __launch_bounds__(256) conv_a_kernel(
    const float* __restrict__ X, __half* __restrict__ A2)
{
    const int idx = blockIdx.x * 256 + threadIdx.x;
    if (idx >= NN * 512) return;
    const int n = idx >> 9, k = idx & 511;
    A2[(size_t)n * 1024 + k] = __float2half_rn(X[idx]);
}

__global__ void __launch_bounds__(256) lstm_first_kernel(
    const float* __restrict__ Xp, const int* __restrict__ src,
    float* __restrict__ c, __half* __restrict__ hout)
{
    const int idx = blockIdx.x * 256 + threadIdx.x;
    if (idx >= NN * 512) return;
    const int n = idx >> 9, hc = idx & 511;
    const int s = src[n * DEG];
    const float4 xv = *(const float4*)(Xp + (size_t)s * 2048 + 4 * hc);
    const float cn = sig_(xv.x) * tanh_(xv.z);
    c[idx] = cn;
    hout[idx] = __float2half_rn(sig_(xv.w) * tanh_(cn));
}

// ---------------------------------------------------------------------------
extern "C" void kernel_launch(void* const* d_in, const int* in_sizes, int n_in,
                              void* d_out, int out_size)
{
    const float* x      = (const float*)d_in[0];
    const int*   src    = (const int*)  d_in[1];
    const float* Wih1   = (const float*)d_in[2];
    const float* Whh1   = (const float*)d_in[3];
    const float* bih1   = (const float*)d_in[4];
    const float* bhh1   = (const float*)d_in[5];
    const float* Wself  = (const float*)d_in[6];
    const float* Wneigh = (const float*)d_in[7];
    const float* b      = (const float*)d_in[8];
    const float* Wih2   = (const float*)d_in[9];
    const float* Whh2   = (const float*)d_in[10];
    const float* bih2   = (const float*)d_in[11];
    const float* bhh2   = (const float*)d_in[12];
    float* out = (float*)d_out;

    float *Xp, *bsum1, *bsum2, *c;
    __half *sageA, *hA, *hB, *hs16, *Wih1b, *Whh1b, *Wih2b, *Whh2b, *WbS;
    unsigned* ctr;
    cudaGetSymbolAddress((void**)&Xp,    g_Xp);
    cudaGetSymbolAddress((void**)&sageA, g_sageA);
    cudaGetSymbolAddress((void**)&hA,    g_hA);
    cudaGetSymbolAddress((void**)&hB,    g_hB);
    cudaGetSymbolAddress((void**)&hs16,  g_hs16);
    cudaGetSymbolAddress((void**)&Wih1b, g_Wih1b);
    cudaGetSymbolAddress((void**)&Whh1b, g_Whh1b);
    cudaGetSymbolAddress((void**)&Wih2b, g_Wih2b);
    cudaGetSymbolAddress((void**)&Whh2b, g_Whh2b);
    cudaGetSymbolAddress((void**)&WbS,   g_WbS);
    cudaGetSymbolAddress((void**)&bsum1, g_bsum1);
    cudaGetSymbolAddress((void**)&bsum2, g_bsum2);
    cudaGetSymbolAddress((void**)&c,     g_c);
    cudaGetSymbolAddress((void**)&ctr,   g_ctr);

    cudaFuncSetAttribute(gemm_f16_kernel,
                         cudaFuncAttributeMaxDynamicSharedMemorySize, SMEMB);
    cudaFuncSetAttribute(lstm_chain_kernel,
                         cudaFuncAttributeMaxDynamicSharedMemorySize, SMEMB);

    const dim3 gMain((NN + 127) / 128, 16);   // 2048 / 128
    const dim3 gSage((NN + 127) / 128, 4);    // 512 / 128
    const int  gElem  = (NN * 512) / 256;
    const int  gConvW = (2048 * 512) / 256;
    const int  gConvS = (512 * 1024) / 256;

    cudaMemsetAsync(ctr, 0, 64 * sizeof(unsigned));                         // barrier reset (captured)

    // ================= Stage 1 =================
    conv_a_kernel<<<gElem, 256>>>(x, sageA);                                // #1
    conv_w_kernel<<<gConvW, 256>>>(Wih1, bih1, bhh1, Wih1b, bsum1);         // #2
    conv_w_kernel<<<gConvW, 256>>>(Whh1, nullptr, nullptr, Whh1b, nullptr); // #3
    gemm_f16_kernel<<<gMain, 256, SMEMB>>>(sageA, 1024, Wih1b, 512, 0,
        bsum1, Xp, nullptr, 0, 0);                                          // #4
    lstm_first_kernel<<<gElem, 256>>>(Xp, src, c, hB);                      // #5? (memset counts as node)
    // persistent chain: t=1..31, final -> sageA cols 512..1023
    lstm_chain_kernel<<<NCTA, 256, SMEMB>>>(Whh1b, Xp, src, c, hA, hB,
        sageA, 1024, 512, nullptr, 0);

    // ---- SAGE linear ----
    conv_w_sage_kernel<<<gConvS, 256>>>(Wself, Wneigh, WbS);
    gemm_f16_kernel<<<gSage, 256, SMEMB>>>(sageA, 1024, WbS, 1024, 2,
        b, nullptr, hs16, 512, 0);

    // ================= Stage 2 =================
    conv_w_kernel<<<gConvW, 256>>>(Wih2, bih2, bhh2, Wih2b, bsum2);
    conv_w_kernel<<<gConvW, 256>>>(Whh2, nullptr, nullptr, Whh2b, nullptr);
    gemm_f16_kernel<<<gMain, 256, SMEMB>>>(hs16, 512, Wih2b, 512, 0,
        bsum2, Xp, nullptr, 0, 0);
    lstm_first_kernel<<<gElem, 256>>>(Xp, src, c, hB);
    lstm_chain_kernel<<<NCTA, 256, SMEMB>>>(Whh2b, Xp, src, c, hA, hB,
        nullptr, 0, 0, out, 32);
}

// round 14
// speedup vs baseline: 1.4413x; 1.4413x over previous
#include <cuda_runtime.h>
#include <cuda_fp16.h>
#include <cstdint>

#define NN   10000
#define DEG  32
#define FF   512

// ---------------- scratch (static device globals; no allocation) ----------
static __device__ float  g_Xp   [(size_t)NN * 2048];   // gate pre-activations (col = 4*hc+gate)
static __device__ __half g_sageA[(size_t)NN * 1024];   // [x_h | hn_h]
static __device__ __half g_hA   [(size_t)NN * 512];    // h fp16 ping
static __device__ __half g_hB   [(size_t)NN * 512];    // h fp16 pong
static __device__ __half g_hs16 [(size_t)NN * 512];    // sage output fp16
static __device__ __half g_Wih1b[(size_t)2048 * 512];  // plain fp16 weights (interleaved rows)
static __device__ __half g_Whh1b[(size_t)2048 * 512];
static __device__ __half g_Wih2b[(size_t)2048 * 512];
static __device__ __half g_Whh2b[(size_t)2048 * 512];
static __device__ __half g_WbS  [(size_t)512 * 1024];  // sage W fp16 [j][k], k<512 Wself, else Wneigh
static __device__ float  g_bsum1[2048];
static __device__ float  g_bsum2[2048];
static __device__ float  g_c    [(size_t)NN * FF];

__device__ __forceinline__ float sig_(float x) {
    return __fdividef(1.0f, 1.0f + __expf(-x));
}
__device__ __forceinline__ float tanh_(float x) {
    float e = __expf(-2.0f * fabsf(x));
    float t = __fdividef(1.0f - e, 1.0f + e);
    return copysignf(t, x);
}
__device__ __forceinline__ uint32_t smem_u32(const void* p) {
    uint32_t a;
    asm("{ .reg .u64 t; cvta.to.shared.u64 t, %1; cvt.u32.u64 %0, t; }" : "=r"(a) : "l"(p));
    return a;
}
__device__ __forceinline__ void cpa16(uint32_t saddr, const void* g, int ss) {
    asm volatile("cp.async.cg.shared.global [%0], [%1], 16, %2;"
                 :: "r"(saddr), "l"(g), "r"(ss) : "memory");
}
__device__ __forceinline__ void ldsm4(uint32_t* r, uint32_t addr) {
    asm volatile("ldmatrix.sync.aligned.m8n8.x4.shared.b16 {%0,%1,%2,%3}, [%4];"
                 : "=r"(r[0]), "=r"(r[1]), "=r"(r[2]), "=r"(r[3]) : "r"(addr));
}
__device__ __forceinline__ void mma16816(float* d, const uint32_t* a, const uint32_t* b) {
    asm volatile("mma.sync.aligned.m16n8k16.row.col.f32.f16.f16.f32 "
                 "{%0,%1,%2,%3}, {%4,%5,%6,%7}, {%8,%9}, {%0,%1,%2,%3};"
                 : "+f"(d[0]), "+f"(d[1]), "+f"(d[2]), "+f"(d[3])
                 : "r"(a[0]), "r"(a[1]), "r"(a[2]), "r"(a[3]), "r"(b[0]), "r"(b[1]));
}

// geometry: block 128x64, 256 threads (8 warps: wm 0..3 x wn 0..1), warp 32x32
// stage = K=64 slab: A 128x64 + B 64x64, PAD 72 halfs/row
#define PAD      72
#define A_TILE_B 18432             // 128*72*2
#define B_TILE_B 9216              // 64*72*2
#define STAGE_B  27648
#define NSTAGE   4
#define SRC_B    512
#define SMEMB    (NSTAGE * STAGE_B + SRC_B)   // 111,104 (x2 CTAs = 222.2KB)

// ---------------------------------------------------------------------------
// GEMM: C[m, n] = A[m,:K] . B[n,:K]   (fp16 x fp16 -> fp32)
// mode 0: Xp[r*2048 + c] = C + bias[c]
// mode 1: LSTM gate epilogue (Xp gather, c update, h fp16 / fp32 out)
// mode 2: hout fp16 = C + bias[c]
// ---------------------------------------------------------------------------
__global__ void __launch_bounds__(256, 2) gemm_f16_kernel(
    const __half* __restrict__ A, int lda,
    const __half* __restrict__ B2, int K, int mode,
    const float* __restrict__ bias, float* __restrict__ XpOut,
    const float* __restrict__ XpIn, const int* __restrict__ src, int t,
    float* __restrict__ cbuf,
    __half* __restrict__ hout, int hstride, int hoff,
    float* __restrict__ h32out)
{
    extern __shared__ __align__(16) char smem[];
    const uint32_t sbase = smem_u32(smem);
    int* const sSrc = (int*)(smem + NSTAGE * STAGE_B);
    const int tid  = threadIdx.x;
    const int warp = tid >> 5, lane = tid & 31;
    const int wn = warp & 1, wm = warp >> 1;
    const int m0 = blockIdx.x * 128, n0 = blockIdx.y * 64;
    const int nst = K >> 6;             // K=64 per stage

    if (mode == 1 && tid < 128) {
        const int rr = m0 + tid;
        sSrc[tid] = (rr < NN) ? src[rr * DEG + t] : 0;
    }

    float accP[2][4][4];
    #pragma unroll
    for (int mi = 0; mi < 2; mi++)
        #pragma unroll
        for (int nj = 0; nj < 4; nj++)
            #pragma unroll
            for (int r = 0; r < 4; r++) accP[mi][nj][r] = 0.f;

    // loads per stage (K=64 halfs = 128B/row): seg8 = 16B chunk within row
    const int rA = tid >> 3, seg8 = tid & 7;
    int aszv[4]; size_t aGv[4]; uint32_t aSmv[4];
    #pragma unroll
    for (int i = 0; i < 4; i++) {
        const int r = rA + i * 32;
        aszv[i] = (m0 + r < NN) ? 16 : 0;
        aGv[i]  = (size_t)((m0 + r < NN) ? (m0 + r) : 0) * lda + seg8 * 8;
        aSmv[i] = (uint32_t)(r * PAD + seg8 * 8) * 2;
    }
    size_t bGv[2]; uint32_t bSmv[2];
    #pragma unroll
    for (int i = 0; i < 2; i++) {
        const int r = rA + i * 32;
        bGv[i]  = (size_t)(n0 + r) * K + seg8 * 8;
        bSmv[i] = (uint32_t)(r * PAD + seg8 * 8) * 2;
    }

    // ldmatrix lane offsets
    const uint32_t aL = (uint32_t)((lane & 15) * PAD + (lane >> 4) * 8) * 2;
    const uint32_t bL = (uint32_t)(((lane & 7) + ((lane >> 4) << 3)) * PAD
                                   + ((lane >> 3) & 1) * 8) * 2;
    const uint32_t aWm = (uint32_t)(wm * 32 * PAD) * 2;
    const uint32_t bWn = (uint32_t)(wn * 32 * PAD) * 2;

    auto issue = [&](int st, int buf) {
        const int kc = st << 6;         // 64 halfs per stage
        const uint32_t s0 = sbase + buf * STAGE_B;
        #pragma unroll
        for (int i = 0; i < 4; i++)
            cpa16(s0 + aSmv[i], A + aGv[i] + kc, aszv[i]);
        #pragma unroll
        for (int i = 0; i < 2; i++)
            cpa16(s0 + A_TILE_B + bSmv[i], B2 + bGv[i] + kc, 16);
        asm volatile("cp.async.commit_group;" ::: "memory");
    };

    issue(0, 0);
    if (nst > 1) issue(1, 1);
    int buf = 0;
    #pragma unroll 1
    for (int st = 0; st < nst; st++) {
        if (st + 1 < nst)
            asm volatile("cp.async.wait_group 1;" ::: "memory");
        else
            asm volatile("cp.async.wait_group 0;" ::: "memory");
        __syncthreads();
        if (st + 2 < nst) {
            int nb = buf + 2; if (nb >= NSTAGE) nb -= NSTAGE;
            issue(st + 2, nb);
        }
        const uint32_t s0 = sbase + buf * STAGE_B;
        #pragma unroll
        for (int ks = 0; ks < 4; ks++) {
            uint32_t aH[2][4], bH[2][4];
            #pragma unroll
            for (int mi = 0; mi < 2; mi++)
                ldsm4(aH[mi], s0 + aWm + aL + (uint32_t)(mi * 16 * PAD + ks * 16) * 2);
            #pragma unroll
            for (int njp = 0; njp < 2; njp++)
                ldsm4(bH[njp], s0 + A_TILE_B + bWn + bL + (uint32_t)(njp * 16 * PAD + ks * 16) * 2);
            #pragma unroll
            for (int mi = 0; mi < 2; mi++)
                #pragma unroll
                for (int nj = 0; nj < 4; nj++)
                    mma16816(accP[mi][nj], aH[mi], &bH[nj >> 1][(nj & 1) * 2]);
        }
        buf++; if (buf >= NSTAGE) buf -= NSTAGE;
    }

    if (mode != 1) {
        #pragma unroll
        for (int mi = 0; mi < 2; mi++)
            #pragma unroll
            for (int nj = 0; nj < 4; nj++) {
                const int c0 = n0 + wn * 32 + nj * 8 + (lane & 3) * 2;
                const int rr = m0 + wm * 32 + mi * 16 + (lane >> 2);
                const float2 bs = make_float2(bias[c0], bias[c0 + 1]);
                float v0 = accP[mi][nj][0] + bs.x;
                float v1 = accP[mi][nj][1] + bs.y;
                float v2 = accP[mi][nj][2] + bs.x;
                float v3 = accP[mi][nj][3] + bs.y;
                if (mode == 0) {
                    if (rr < NN)     *(float2*)(XpOut + (size_t)rr * 2048 + c0) = make_float2(v0, v1);
                    if (rr + 8 < NN) *(float2*)(XpOut + (size_t)(rr + 8) * 2048 + c0) = make_float2(v2, v3);
                } else {
                    if (rr < NN)
                        *(__half2*)(hout + (size_t)rr * hstride + hoff + c0) =
                            __halves2half2(__float2half_rn(v0), __float2half_rn(v1));
                    if (rr + 8 < NN)
                        *(__half2*)(hout + (size_t)(rr + 8) * hstride + hoff + c0) =
                            __halves2half2(__float2half_rn(v2), __float2half_rn(v3));
                }
            }
    } else {
        #pragma unroll
        for (int mi = 0; mi < 2; mi++)
            #pragma unroll
            for (int nj = 0; nj < 4; nj++) {
                float v0 = accP[mi][nj][0];
                float v1 = accP[mi][nj][1];
                float v2 = accP[mi][nj][2];
                float v3 = accP[mi][nj][3];
                const float p0 = __shfl_xor_sync(0xffffffffu, v0, 1);
                const float p1 = __shfl_xor_sync(0xffffffffu, v1, 1);
                const float p2 = __shfl_xor_sync(0xffffffffu, v2, 1);
                const float p3 = __shfl_xor_sync(0xffffffffu, v3, 1);
                const int q = lane & 1;
                const int rl = wm * 32 + mi * 16 + (lane >> 2) + (q << 3);
                const int rowU = m0 + rl;
                const int hc = ((n0 + wn * 32 + nj * 8) >> 2) + ((lane & 3) >> 1);
                if (rowU < NN) {
                    float gi, gf, gg, go;
                    if (!q) { gi = v0; gf = v1; gg = p0; go = p1; }
                    else    { gi = p2; gf = p3; gg = v2; go = v3; }
                    const int s = sSrc[rl];
                    const float4 xv = *(const float4*)(XpIn + (size_t)s * 2048 + 4 * hc);
                    gi += xv.x; gf += xv.y; gg += xv.z; go += xv.w;
                    const size_t ci = (size_t)rowU * FF + hc;
                    const float cn = sig_(gf) * cbuf[ci] + sig_(gi) * tanh_(gg);
                    cbuf[ci] = cn;
                    const float hv = sig_(go) * tanh_(cn);
                    if (h32out) h32out[ci] = hv;
                    if (hout) hout[(size_t)rowU * hstride + hoff + hc] = __float2half_rn(hv);
                }
            }
    }
}

// ---------------------------------------------------------------------------
// conv_w: W fp32 [2048,512] (rows gate*512+hc) -> fp16 [2048][512] interleaved
// row jp = 4*hc + gate; bsum[jp] = b1 + b2
// ---------------------------------------------------------------------------
__global__ void __launch_bounds__(256) conv_w_kernel(
    const float* __restrict__ W, const float* __restrict__ b1, const float* __restrict__ b2,
    __half* __restrict__ W2, float* __restrict__ bsum)
{
    const int idx = blockIdx.x * 256 + threadIdx.x;
    if (idx >= 2048 * 512) return;
    const int jp = idx >> 9, k = idx & 511;
    const int orig = (jp & 3) * 512 + (jp >> 2);
    W2[(size_t)jp * 512 + k] = __float2half_rn(W[(size_t)orig * 512 + k]);
    if (k == 0 && bsum) bsum[jp] = b1[orig] + b2[orig];
}

// conv_w_sage: WbS[512][1024]: row j, k<512 -> Wself[k,j]; k>=512 -> Wneigh[k-512,j]
__global__ void __launch_bounds__(256) conv_w_sage_kernel(
    const float* __restrict__ Ws, const float* __restrict__ Wn,
    __half* __restrict__ W2)
{
    const int idx = blockIdx.x * 256 + threadIdx.x;
    if (idx >= 512 * 1024) return;
    const int j = idx >> 10, k = idx & 1023;
    const float w = (k < 512) ? Ws[(size_t)k * 512 + j] : Wn[(size_t)(k - 512) * 512 + j];
    W2[(size_t)j * 1024 + k] = __float2half_rn(w);
}

// conv_a: x fp32 -> fp16 into sageA cols 0..511 (stride 1024)
__global__ void __launch_bounds__(256) conv_a_kernel(
    const float* __restrict__ X, __half* __restrict__ A2)
{
    const int idx = blockIdx.x * 256 + threadIdx.x;
    if (idx >= NN * 512) return;
    const int n = idx >> 9, k = idx & 511;
    A2[(size_t)n * 1024 + k] = __float2half_rn(X[idx]);
}

// first LSTM step (t=0): gates = Xp[src[:,0]]; write c + h fp16
__global__ void __launch_bounds__(256) lstm_first_kernel(
    const float* __restrict__ Xp, const int* __restrict__ src,
    float* __restrict__ c, __half* __restrict__ hout)
{
    const int idx = blockIdx.x * 256 + threadIdx.x;
    if (idx >= NN * 512) return;
    const int n = idx >> 9, hc = idx & 511;
    const int s = src[n * DEG];
    const float4 xv = *(const float4*)(Xp + (size_t)s * 2048 + 4 * hc);
    const float cn = sig_(xv.x) * tanh_(xv.z);
    c[idx] = cn;
    hout[idx] = __float2half_rn(sig_(xv.w) * tanh_(cn));
}

// ---------------------------------------------------------------------------
extern "C" void kernel_launch(void* const* d_in, const int* in_sizes, int n_in,
                              void* d_out, int out_size)
{
    const float* x      = (const float*)d_in[0];
    const int*   src    = (const int*)  d_in[1];
    const float* Wih1   = (const float*)d_in[2];
    const float* Whh1   = (const float*)d_in[3];
    const float* bih1   = (const float*)d_in[4];
    const float* bhh1   = (const float*)d_in[5];
    const float* Wself  = (const float*)d_in[6];
    const float* Wneigh = (const float*)d_in[7];
    const float* b      = (const float*)d_in[8];
    const float* Wih2   = (const float*)d_in[9];
    const float* Whh2   = (const float*)d_in[10];
    const float* bih2   = (const float*)d_in[11];
    const float* bhh2   = (const float*)d_in[12];
    float* out = (float*)d_out;

    float *Xp, *bsum1, *bsum2, *c;
    __half *sageA, *hA, *hB, *hs16, *Wih1b, *Whh1b, *Wih2b, *Whh2b, *WbS;
    cudaGetSymbolAddress((void**)&Xp,    g_Xp);
    cudaGetSymbolAddress((void**)&sageA, g_sageA);
    cudaGetSymbolAddress((void**)&hA,    g_hA);
    cudaGetSymbolAddress((void**)&hB,    g_hB);
    cudaGetSymbolAddress((void**)&hs16,  g_hs16);
    cudaGetSymbolAddress((void**)&Wih1b, g_Wih1b);
    cudaGetSymbolAddress((void**)&Whh1b, g_Whh1b);
    cudaGetSymbolAddress((void**)&Wih2b, g_Wih2b);
    cudaGetSymbolAddress((void**)&Whh2b, g_Whh2b);
    cudaGetSymbolAddress((void**)&WbS,   g_WbS);
    cudaGetSymbolAddress((void**)&bsum1, g_bsum1);
    cudaGetSymbolAddress((void**)&bsum2, g_bsum2);
    cudaGetSymbolAddress((void**)&c,     g_c);

    cudaFuncSetAttribute(gemm_f16_kernel,
                         cudaFuncAttributeMaxDynamicSharedMemorySize, SMEMB);

    const dim3 gMain((NN + 127) / 128, 32);   // 2048 output cols / 64
    const dim3 gSage((NN + 127) / 128, 8);    // 512 output cols / 64
    const int  gElem  = (NN * 512) / 256;
    const int  gConvW = (2048 * 512) / 256;
    const int  gConvS = (512 * 1024) / 256;

    // Launch order: index 5 (ncu -s 5 -c 1) is the first mode-1 LSTM GEMM step.
    conv_a_kernel<<<gElem, 256>>>(x, sageA);                                // #0
    conv_w_kernel<<<gConvW, 256>>>(Wih1, bih1, bhh1, Wih1b, bsum1);         // #1
    conv_w_kernel<<<gConvW, 256>>>(Whh1, nullptr, nullptr, Whh1b, nullptr); // #2
    gemm_f16_kernel<<<gMain, 256, SMEMB>>>(sageA, 1024, Wih1b, 512, 0,
        bsum1, Xp, nullptr, nullptr, 0, nullptr, nullptr, 0, 0, nullptr);   // #3
    lstm_first_kernel<<<gElem, 256>>>(Xp, src, c, hB);                      // #4
    for (int t = 1; t <= 30; t++) {                                         // #5 = t=1
        __half* hin  = (t & 1) ? hB : hA;
        __half* hout = (t & 1) ? hA : hB;
        gemm_f16_kernel<<<gMain, 256, SMEMB>>>(hin, 512, Whh1b, 512, 1,
            nullptr, nullptr, Xp, src, t, c, hout, 512, 0, nullptr);
    }
    gemm_f16_kernel<<<gMain, 256, SMEMB>>>(hB, 512, Whh1b, 512, 1,
        nullptr, nullptr, Xp, src, 31, c, sageA, 1024, 512, nullptr);

    conv_w_sage_kernel<<<gConvS, 256>>>(Wself, Wneigh, WbS);
    gemm_f16_kernel<<<gSage, 256, SMEMB>>>(sageA, 1024, WbS, 1024, 2,
        b, nullptr, nullptr, nullptr, 0, nullptr, hs16, 512, 0, nullptr);

    conv_w_kernel<<<gConvW, 256>>>(Wih2, bih2, bhh2, Wih2b, bsum2);
    conv_w_kernel<<<gConvW, 256>>>(Whh2, nullptr, nullptr, Whh2b, nullptr);
    gemm_f16_kernel<<<gMain, 256, SMEMB>>>(hs16, 512, Wih2b, 512, 0,
        bsum2, Xp, nullptr, nullptr, 0, nullptr, nullptr, 0, 0, nullptr);
    lstm_first_kernel<<<gElem, 256>>>(Xp, src, c, hB);
    for (int t = 1; t <= 30; t++) {
        __half* hin  = (t & 1) ? hB : hA;
        __half* hout = (t & 1) ? hA : hB;
        gemm_f16_kernel<<<gMain, 256, SMEMB>>>(hin, 512, Whh2b, 512, 1,
            nullptr, nullptr, Xp, src, t, c, hout, 512, 0, nullptr);
    }
    gemm_f16_kernel<<<gMain, 256, SMEMB>>>(hB, 512, Whh2b, 512, 1,
        nullptr, nullptr, Xp, src, 31, c, nullptr, 0, 0, out);
}

// round 15
// speedup vs baseline: 1.7447x; 1.2106x over previous
#include <cuda_runtime.h>
#include <cuda_fp16.h>
#include <cstdint>

#define NN   10000
#define DEG  32
#define FF   512

// ---------------- scratch (static device globals; no allocation) ----------
static __device__ float  g_Xp   [(size_t)NN * 2048];   // gate pre-activations (col = 4*hc+gate)
static __device__ __half g_sageA[(size_t)NN * 1024];   // [x_h | hn_h]
static __device__ __half g_hA   [(size_t)NN * 512];    // h fp16 ping
static __device__ __half g_hB   [(size_t)NN * 512];    // h fp16 pong
static __device__ __half g_hs16 [(size_t)NN * 512];    // sage output fp16
static __device__ __half g_Wih1b[(size_t)2048 * 512];  // plain fp16 weights (interleaved rows)
static __device__ __half g_Whh1b[(size_t)2048 * 512];
static __device__ __half g_Wih2b[(size_t)2048 * 512];
static __device__ __half g_Whh2b[(size_t)2048 * 512];
static __device__ __half g_WbS  [(size_t)512 * 1024];  // sage W fp16 [j][k], k<512 Wself, else Wneigh
static __device__ float  g_bsum1[2048];
static __device__ float  g_bsum2[2048];
static __device__ float  g_c    [(size_t)NN * FF];

__device__ __forceinline__ float sig_(float x) {
    return __fdividef(1.0f, 1.0f + __expf(-x));
}
__device__ __forceinline__ float tanh_(float x) {
    float e = __expf(-2.0f * fabsf(x));
    float t = __fdividef(1.0f - e, 1.0f + e);
    return copysignf(t, x);
}
__device__ __forceinline__ uint32_t smem_u32(const void* p) {
    uint32_t a;
    asm("{ .reg .u64 t; cvta.to.shared.u64 t, %1; cvt.u32.u64 %0, t; }" : "=r"(a) : "l"(p));
    return a;
}
__device__ __forceinline__ void cpa16(uint32_t saddr, const void* g, int ss) {
    asm volatile("cp.async.cg.shared.global [%0], [%1], 16, %2;"
                 :: "r"(saddr), "l"(g), "r"(ss) : "memory");
}
__device__ __forceinline__ void ldsm4(uint32_t* r, uint32_t addr) {
    asm volatile("ldmatrix.sync.aligned.m8n8.x4.shared.b16 {%0,%1,%2,%3}, [%4];"
                 : "=r"(r[0]), "=r"(r[1]), "=r"(r[2]), "=r"(r[3]) : "r"(addr));
}
__device__ __forceinline__ void mma16816(float* d, const uint32_t* a, const uint32_t* b) {
    asm volatile("mma.sync.aligned.m16n8k16.row.col.f32.f16.f16.f32 "
                 "{%0,%1,%2,%3}, {%4,%5,%6,%7}, {%8,%9}, {%0,%1,%2,%3};"
                 : "+f"(d[0]), "+f"(d[1]), "+f"(d[2]), "+f"(d[3])
                 : "r"(a[0]), "r"(a[1]), "r"(a[2]), "r"(a[3]), "r"(b[0]), "r"(b[1]));
}

// geometry: block 128x64, 256 threads (8 warps: wm 0..3 x wn 0..1), warp 32x32
// stage = K=64 slab: A 128x64 + B 64x64, PAD 72 halfs/row
#define PAD      72
#define A_TILE_B 18432             // 128*72*2
#define B_TILE_B 9216              // 64*72*2
#define STAGE_B  27648
#define NSTAGE   3
#define SRC_B    512
#define SMEMB    (NSTAGE * STAGE_B + SRC_B)   // 83,456 (x2 CTAs = 166.9KB; L1D ~61KB)

// ---------------------------------------------------------------------------
// GEMM: C[m, n] = A[m,:K] . B[n,:K]   (fp16 x fp16 -> fp32)
// mode 0: Xp[r*2048 + c] = C + bias[c]
// mode 1: LSTM gate epilogue (Xp gather, c update, h fp16 / fp32 out)
// mode 2: hout fp16 = C + bias[c]
// ---------------------------------------------------------------------------
__global__ void __launch_bounds__(256, 2) gemm_f16_kernel(
    const __half* __restrict__ A, int lda,
    const __half* __restrict__ B2, int K, int mode,
    const float* __restrict__ bias, float* __restrict__ XpOut,
    const float* __restrict__ XpIn, const int* __restrict__ src, int t,
    float* __restrict__ cbuf,
    __half* __restrict__ hout, int hstride, int hoff,
    float* __restrict__ h32out)
{
    extern __shared__ __align__(16) char smem[];
    const uint32_t sbase = smem_u32(smem);
    int* const sSrc = (int*)(smem + NSTAGE * STAGE_B);
    const int tid  = threadIdx.x;
    const int warp = tid >> 5, lane = tid & 31;
    const int wn = warp & 1, wm = warp >> 1;
    const int m0 = blockIdx.x * 128, n0 = blockIdx.y * 64;
    const int nst = K >> 6;             // K=64 per stage

    if (mode == 1 && tid < 128) {
        const int rr = m0 + tid;
        sSrc[tid] = (rr < NN) ? src[rr * DEG + t] : 0;
    }

    float accP[2][4][4];
    #pragma unroll
    for (int mi = 0; mi < 2; mi++)
        #pragma unroll
        for (int nj = 0; nj < 4; nj++)
            #pragma unroll
            for (int r = 0; r < 4; r++) accP[mi][nj][r] = 0.f;

    // loads per stage (K=64 halfs = 128B/row): seg8 = 16B chunk within row
    const int rA = tid >> 3, seg8 = tid & 7;
    int aszv[4]; size_t aGv[4]; uint32_t aSmv[4];
    #pragma unroll
    for (int i = 0; i < 4; i++) {
        const int r = rA + i * 32;
        aszv[i] = (m0 + r < NN) ? 16 : 0;
        aGv[i]  = (size_t)((m0 + r < NN) ? (m0 + r) : 0) * lda + seg8 * 8;
        aSmv[i] = (uint32_t)(r * PAD + seg8 * 8) * 2;
    }
    size_t bGv[2]; uint32_t bSmv[2];
    #pragma unroll
    for (int i = 0; i < 2; i++) {
        const int r = rA + i * 32;
        bGv[i]  = (size_t)(n0 + r) * K + seg8 * 8;
        bSmv[i] = (uint32_t)(r * PAD + seg8 * 8) * 2;
    }

    // ldmatrix lane offsets
    const uint32_t aL = (uint32_t)((lane & 15) * PAD + (lane >> 4) * 8) * 2;
    const uint32_t bL = (uint32_t)(((lane & 7) + ((lane >> 4) << 3)) * PAD
                                   + ((lane >> 3) & 1) * 8) * 2;
    const uint32_t aWm = (uint32_t)(wm * 32 * PAD) * 2;
    const uint32_t bWn = (uint32_t)(wn * 32 * PAD) * 2;

    auto issue = [&](int st, int buf) {
        const int kc = st << 6;         // 64 halfs per stage
        const uint32_t s0 = sbase + buf * STAGE_B;
        #pragma unroll
        for (int i = 0; i < 4; i++)
            cpa16(s0 + aSmv[i], A + aGv[i] + kc, aszv[i]);
        #pragma unroll
        for (int i = 0; i < 2; i++)
            cpa16(s0 + A_TILE_B + bSmv[i], B2 + bGv[i] + kc, 16);
        asm volatile("cp.async.commit_group;" ::: "memory");
    };

    issue(0, 0);
    if (nst > 1) issue(1, 1);
    int buf = 0;
    #pragma unroll 1
    for (int st = 0; st < nst; st++) {
        if (st + 1 < nst)
            asm volatile("cp.async.wait_group 1;" ::: "memory");
        else
            asm volatile("cp.async.wait_group 0;" ::: "memory");
        __syncthreads();
        if (st + 2 < nst) {
            int nb = buf + 2; if (nb >= NSTAGE) nb -= NSTAGE;
            issue(st + 2, nb);
        }
        const uint32_t s0 = sbase + buf * STAGE_B;
        #pragma unroll
        for (int ks = 0; ks < 4; ks++) {
            uint32_t aH[2][4], bH[2][4];
            #pragma unroll
            for (int mi = 0; mi < 2; mi++)
                ldsm4(aH[mi], s0 + aWm + aL + (uint32_t)(mi * 16 * PAD + ks * 16) * 2);
            #pragma unroll
            for (int njp = 0; njp < 2; njp++)
                ldsm4(bH[njp], s0 + A_TILE_B + bWn + bL + (uint32_t)(njp * 16 * PAD + ks * 16) * 2);
            #pragma unroll
            for (int mi = 0; mi < 2; mi++)
                #pragma unroll
                for (int nj = 0; nj < 4; nj++)
                    mma16816(accP[mi][nj], aH[mi], &bH[nj >> 1][(nj & 1) * 2]);
        }
        buf++; if (buf >= NSTAGE) buf -= NSTAGE;
    }

    if (mode != 1) {
        #pragma unroll
        for (int mi = 0; mi < 2; mi++)
            #pragma unroll
            for (int nj = 0; nj < 4; nj++) {
                const int c0 = n0 + wn * 32 + nj * 8 + (lane & 3) * 2;
                const int rr = m0 + wm * 32 + mi * 16 + (lane >> 2);
                const float2 bs = make_float2(bias[c0], bias[c0 + 1]);
                float v0 = accP[mi][nj][0] + bs.x;
                float v1 = accP[mi][nj][1] + bs.y;
                float v2 = accP[mi][nj][2] + bs.x;
                float v3 = accP[mi][nj][3] + bs.y;
                if (mode == 0) {
                    if (rr < NN)     *(float2*)(XpOut + (size_t)rr * 2048 + c0) = make_float2(v0, v1);
                    if (rr + 8 < NN) *(float2*)(XpOut + (size_t)(rr + 8) * 2048 + c0) = make_float2(v2, v3);
                } else {  // mode 2: fp16 write
                    if (rr < NN)
                        *(__half2*)(hout + (size_t)rr * hstride + hoff + c0) =
                            __halves2half2(__float2half_rn(v0), __float2half_rn(v1));
                    if (rr + 8 < NN)
                        *(__half2*)(hout + (size_t)(rr + 8) * hstride + hoff + c0) =
                            __halves2half2(__float2half_rn(v2), __float2half_rn(v3));
                }
            }
    } else {
        #pragma unroll
        for (int mi = 0; mi < 2; mi++)
            #pragma unroll
            for (int nj = 0; nj < 4; nj++) {
                float v0 = accP[mi][nj][0];
                float v1 = accP[mi][nj][1];
                float v2 = accP[mi][nj][2];
                float v3 = accP[mi][nj][3];
                const float p0 = __shfl_xor_sync(0xffffffffu, v0, 1);
                const float p1 = __shfl_xor_sync(0xffffffffu, v1, 1);
                const float p2 = __shfl_xor_sync(0xffffffffu, v2, 1);
                const float p3 = __shfl_xor_sync(0xffffffffu, v3, 1);
                const int q = lane & 1;
                const int rl = wm * 32 + mi * 16 + (lane >> 2) + (q << 3);
                const int rowU = m0 + rl;
                const int hc = ((n0 + wn * 32 + nj * 8) >> 2) + ((lane & 3) >> 1);
                if (rowU < NN) {
                    float gi, gf, gg, go;
                    if (!q) { gi = v0; gf = v1; gg = p0; go = p1; }
                    else    { gi = p2; gf = p3; gg = v2; go = v3; }
                    const int s = sSrc[rl];
                    const float4 xv = *(const float4*)(XpIn + (size_t)s * 2048 + 4 * hc);
                    gi += xv.x; gf += xv.y; gg += xv.z; go += xv.w;
                    const size_t ci = (size_t)rowU * FF + hc;
                    const float cn = sig_(gf) * cbuf[ci] + sig_(gi) * tanh_(gg);
                    cbuf[ci] = cn;
                    const float hv = sig_(go) * tanh_(cn);
                    if (h32out) h32out[ci] = hv;
                    if (hout) hout[(size_t)rowU * hstride + hoff + hc] = __float2half_rn(hv);
                }
            }
    }
}

// ---------------------------------------------------------------------------
// conv_w: W fp32 [2048,512] (rows gate*512+hc) -> fp16 [2048][512] interleaved
// row jp = 4*hc + gate; bsum[jp] = b1 + b2
// ---------------------------------------------------------------------------
__global__ void __launch_bounds__(256) conv_w_kernel(
    const float* __restrict__ W, const float* __restrict__ b1, const float* __restrict__ b2,
    __half* __restrict__ W2, float* __restrict__ bsum)
{
    const int idx = blockIdx.x * 256 + threadIdx.x;
    if (idx >= 2048 * 512) return;
    const int jp = idx >> 9, k = idx & 511;
    const int orig = (jp & 3) * 512 + (jp >> 2);
    W2[(size_t)jp * 512 + k] = __float2half_rn(W[(size_t)orig * 512 + k]);
    if (k == 0 && bsum) bsum[jp] = b1[orig] + b2[orig];
}

// conv_w_sage: WbS[512][1024]: row j, k<512 -> Wself[k,j]; k>=512 -> Wneigh[k-512,j]
__global__ void __launch_bounds__(256) conv_w_sage_kernel(
    const float* __restrict__ Ws, const float* __restrict__ Wn,
    __half* __restrict__ W2)
{
    const int idx = blockIdx.x * 256 + threadIdx.x;
    if (idx >= 512 * 1024) return;
    const int j = idx >> 10, k = idx & 1023;
    const float w = (k < 512) ? Ws[(size_t)k * 512 + j] : Wn[(size_t)(k - 512) * 512 + j];
    W2[(size_t)j * 1024 + k] = __float2half_rn(w);
}

// conv_a: x fp32 -> fp16 into sageA cols 0..511 (stride 1024)
__global__ void __launch_bounds__(256) conv_a_kernel(
    const float* __restrict__ X, __half* __restrict__ A2)
{
    const int idx = blockIdx.x * 256 + threadIdx.x;
    if (idx >= NN * 512) return;
    const int n = idx >> 9, k = idx & 511;
    A2[(size_t)n * 1024 + k] = __float2half_rn(X[idx]);
}

// first LSTM step (t=0): gates = Xp[src[:,0]]; write c + h fp16
__global__ void __launch_bounds__(256) lstm_first_kernel(
    const float* __restrict__ Xp, const int* __restrict__ src,
    float* __restrict__ c, __half* __restrict__ hout)
{
    const int idx = blockIdx.x * 256 + threadIdx.x;
    if (idx >= NN * 512) return;
    const int n = idx >> 9, hc = idx & 511;
    const int s = src[n * DEG];
    const float4 xv = *(const float4*)(Xp + (size_t)s * 2048 + 4 * hc);
    const float cn = sig_(xv.x) * tanh_(xv.z);
    c[idx] = cn;
    hout[idx] = __float2half_rn(sig_(xv.w) * tanh_(cn));
}

// ---------------------------------------------------------------------------
extern "C" void kernel_launch(void* const* d_in, const int* in_sizes, int n_in,
                              void* d_out, int out_size)
{
    const float* x      = (const float*)d_in[0];
    const int*   src    = (const int*)  d_in[1];
    const float* Wih1   = (const float*)d_in[2];
    const float* Whh1   = (const float*)d_in[3];
    const float* bih1   = (const float*)d_in[4];
    const float* bhh1   = (const float*)d_in[5];
    const float* Wself  = (const float*)d_in[6];
    const float* Wneigh = (const float*)d_in[7];
    const float* b      = (const float*)d_in[8];
    const float* Wih2   = (const float*)d_in[9];
    const float* Whh2   = (const float*)d_in[10];
    const float* bih2   = (const float*)d_in[11];
    const float* bhh2   = (const float*)d_in[12];
    float* out = (float*)d_out;

    float *Xp, *bsum1, *bsum2, *c;
    __half *sageA, *hA, *hB, *hs16, *Wih1b, *Whh1b, *Wih2b, *Whh2b, *WbS;
    cudaGetSymbolAddress((void**)&Xp,    g_Xp);
    cudaGetSymbolAddress((void**)&sageA, g_sageA);
    cudaGetSymbolAddress((void**)&hA,    g_hA);
    cudaGetSymbolAddress((void**)&hB,    g_hB);
    cudaGetSymbolAddress((void**)&hs16,  g_hs16);
    cudaGetSymbolAddress((void**)&Wih1b, g_Wih1b);
    cudaGetSymbolAddress((void**)&Whh1b, g_Whh1b);
    cudaGetSymbolAddress((void**)&Wih2b, g_Wih2b);
    cudaGetSymbolAddress((void**)&Whh2b, g_Whh2b);
    cudaGetSymbolAddress((void**)&WbS,   g_WbS);
    cudaGetSymbolAddress((void**)&bsum1, g_bsum1);
    cudaGetSymbolAddress((void**)&bsum2, g_bsum2);
    cudaGetSymbolAddress((void**)&c,     g_c);

    cudaFuncSetAttribute(gemm_f16_kernel,
                         cudaFuncAttributeMaxDynamicSharedMemorySize, SMEMB);

    const dim3 gMain((NN + 127) / 128, 32);   // 2048 output cols / 64
    const dim3 gSage((NN + 127) / 128, 8);    // 512 output cols / 64
    const int  gElem  = (NN * 512) / 256;
    const int  gConvW = (2048 * 512) / 256;
    const int  gConvS = (512 * 1024) / 256;

    // Launch order: index 5 (ncu -s 5 -c 1) is the first mode-1 LSTM GEMM step.
    conv_a_kernel<<<gElem, 256>>>(x, sageA);                                // #0
    conv_w_kernel<<<gConvW, 256>>>(Wih1, bih1, bhh1, Wih1b, bsum1);         // #1
    conv_w_kernel<<<gConvW, 256>>>(Whh1, nullptr, nullptr, Whh1b, nullptr); // #2
    gemm_f16_kernel<<<gMain, 256, SMEMB>>>(sageA, 1024, Wih1b, 512, 0,
        bsum1, Xp, nullptr, nullptr, 0, nullptr, nullptr, 0, 0, nullptr);   // #3
    lstm_first_kernel<<<gElem, 256>>>(Xp, src, c, hB);                      // #4
    for (int t = 1; t <= 30; t++) {                                         // #5 = t=1
        __half* hin  = (t & 1) ? hB : hA;
        __half* hout = (t & 1) ? hA : hB;
        gemm_f16_kernel<<<gMain, 256, SMEMB>>>(hin, 512, Whh1b, 512, 1,
            nullptr, nullptr, Xp, src, t, c, hout, 512, 0, nullptr);
    }
    gemm_f16_kernel<<<gMain, 256, SMEMB>>>(hB, 512, Whh1b, 512, 1,
        nullptr, nullptr, Xp, src, 31, c, sageA, 1024, 512, nullptr);

    conv_w_sage_kernel<<<gConvS, 256>>>(Wself, Wneigh, WbS);
    gemm_f16_kernel<<<gSage, 256, SMEMB>>>(sageA, 1024, WbS, 1024, 2,
        b, nullptr, nullptr, nullptr, 0, nullptr, hs16, 512, 0, nullptr);

    conv_w_kernel<<<gConvW, 256>>>(Wih2, bih2, bhh2, Wih2b, bsum2);
    conv_w_kernel<<<gConvW, 256>>>(Whh2, nullptr, nullptr, Whh2b, nullptr);
    gemm_f16_kernel<<<gMain, 256, SMEMB>>>(hs16, 512, Wih2b, 512, 0,
        bsum2, Xp, nullptr, nullptr, 0, nullptr, nullptr, 0, 0, nullptr);
    lstm_first_kernel<<<gElem, 256>>>(Xp, src, c, hB);
    for (int t = 1; t <= 30; t++) {
        __half* hin  = (t & 1) ? hB : hA;
        __half* hout = (t & 1) ? hA : hB;
        gemm_f16_kernel<<<gMain, 256, SMEMB>>>(hin, 512, Whh2b, 512, 1,
            nullptr, nullptr, Xp, src, t, c, hout, 512, 0, nullptr);
    }
    gemm_f16_kernel<<<gMain, 256, SMEMB>>>(hB, 512, Whh2b, 512, 1,
        nullptr, nullptr, Xp, src, 31, c, nullptr, 0, 0, out);
}

// round 17
// speedup vs baseline: 1.8020x; 1.0328x over previous
#include <cuda_runtime.h>
#include <cuda_fp16.h>
#include <cstdint>

#define NN   10000
#define DEG  32
#define FF   512

// ---------------- scratch (static device globals; no allocation) ----------
static __device__ float  g_Xp   [(size_t)NN * 2048];   // gate pre-activations (col = 4*hc+gate)
static __device__ __half g_sageA[(size_t)NN * 1024];   // [x_h | hn_h]
static __device__ __half g_hA   [(size_t)NN * 512];    // h fp16 ping
static __device__ __half g_hB   [(size_t)NN * 512];    // h fp16 pong
static __device__ __half g_hs16 [(size_t)NN * 512];    // sage output fp16
static __device__ __half g_Wih1b[(size_t)2048 * 512];  // plain fp16 weights (interleaved rows)
static __device__ __half g_Whh1b[(size_t)2048 * 512];
static __device__ __half g_Wih2b[(size_t)2048 * 512];
static __device__ __half g_Whh2b[(size_t)2048 * 512];
static __device__ __half g_WbS  [(size_t)512 * 1024];  // sage W fp16 [j][k], k<512 Wself, else Wneigh
static __device__ float  g_bsum1[2048];
static __device__ float  g_bsum2[2048];
static __device__ float  g_c    [(size_t)NN * FF];

__device__ __forceinline__ float sig_(float x) {
    return __fdividef(1.0f, 1.0f + __expf(-x));
}
__device__ __forceinline__ float tanh_(float x) {
    float e = __expf(-2.0f * fabsf(x));
    float t = __fdividef(1.0f - e, 1.0f + e);
    return copysignf(t, x);
}
__device__ __forceinline__ uint32_t smem_u32(const void* p) {
    uint32_t a;
    asm("{ .reg .u64 t; cvta.to.shared.u64 t, %1; cvt.u32.u64 %0, t; }" : "=r"(a) : "l"(p));
    return a;
}
__device__ __forceinline__ void cpa16(uint32_t saddr, const void* g, int ss) {
    asm volatile("cp.async.cg.shared.global [%0], [%1], 16, %2;"
                 :: "r"(saddr), "l"(g), "r"(ss) : "memory");
}
__device__ __forceinline__ void ldsm4(uint32_t* r, uint32_t addr) {
    asm volatile("ldmatrix.sync.aligned.m8n8.x4.shared.b16 {%0,%1,%2,%3}, [%4];"
                 : "=r"(r[0]), "=r"(r[1]), "=r"(r[2]), "=r"(r[3]) : "r"(addr));
}
__device__ __forceinline__ void mma16816(float* d, const uint32_t* a, const uint32_t* b) {
    asm volatile("mma.sync.aligned.m16n8k16.row.col.f32.f16.f16.f32 "
                 "{%0,%1,%2,%3}, {%4,%5,%6,%7}, {%8,%9}, {%0,%1,%2,%3};"
                 : "+f"(d[0]), "+f"(d[1]), "+f"(d[2]), "+f"(d[3])
                 : "r"(a[0]), "r"(a[1]), "r"(a[2]), "r"(a[3]), "r"(b[0]), "r"(b[1]));
}

// geometry: block 128x64, 256 threads (8 warps: wm 0..3 x wn 0..1), warp 32x32
// stage = K=64 slab: A 128x64 + B 64x64, PAD 72 halfs/row
#define PAD      72
#define A_TILE_B 18432             // 128*72*2
#define B_TILE_B 9216              // 64*72*2
#define STAGE_B  27648
#define NSTAGE   2
#define SRC_B    512
#define SMEMB    (NSTAGE * STAGE_B + SRC_B)   // 55,808 (x2 CTAs = 111.6KB; L1D ~116KB)

// ---------------------------------------------------------------------------
// GEMM: C[m, n] = A[m,:K] . B[n,:K]   (fp16 x fp16 -> fp32)
// mode 0: Xp[r*2048 + c] = C + bias[c]
// mode 1: LSTM gate epilogue (Xp gather, c update, h fp16 / fp32 out)
// mode 2: hout fp16 = C + bias[c]
// ---------------------------------------------------------------------------
__global__ void __launch_bounds__(256, 2) gemm_f16_kernel(
    const __half* __restrict__ A, int lda,
    const __half* __restrict__ B2, int K, int mode,
    const float* __restrict__ bias, float* __restrict__ XpOut,
    const float* __restrict__ XpIn, const int* __restrict__ src, int t,
    float* __restrict__ cbuf,
    __half* __restrict__ hout, int hstride, int hoff,
    float* __restrict__ h32out)
{
    extern __shared__ __align__(16) char smem[];
    const uint32_t sbase = smem_u32(smem);
    int* const sSrc = (int*)(smem + NSTAGE * STAGE_B);
    const int tid  = threadIdx.x;
    const int warp = tid >> 5, lane = tid & 31;
    const int wn = warp & 1, wm = warp >> 1;
    const int m0 = blockIdx.x * 128, n0 = blockIdx.y * 64;
    const int nst = K >> 6;             // K=64 per stage

    if (mode == 1 && tid < 128) {
        const int rr = m0 + tid;
        sSrc[tid] = (rr < NN) ? src[rr * DEG + t] : 0;
    }

    float accP[2][4][4];
    #pragma unroll
    for (int mi = 0; mi < 2; mi++)
        #pragma unroll
        for (int nj = 0; nj < 4; nj++)
            #pragma unroll
            for (int r = 0; r < 4; r++) accP[mi][nj][r] = 0.f;

    // loads per stage (K=64 halfs = 128B/row): seg8 = 16B chunk within row
    const int rA = tid >> 3, seg8 = tid & 7;
    int aszv[4]; size_t aGv[4]; uint32_t aSmv[4];
    #pragma unroll
    for (int i = 0; i < 4; i++) {
        const int r = rA + i * 32;
        aszv[i] = (m0 + r < NN) ? 16 : 0;
        aGv[i]  = (size_t)((m0 + r < NN) ? (m0 + r) : 0) * lda + seg8 * 8;
        aSmv[i] = (uint32_t)(r * PAD + seg8 * 8) * 2;
    }
    size_t bGv[2]; uint32_t bSmv[2];
    #pragma unroll
    for (int i = 0; i < 2; i++) {
        const int r = rA + i * 32;
        bGv[i]  = (size_t)(n0 + r) * K + seg8 * 8;
        bSmv[i] = (uint32_t)(r * PAD + seg8 * 8) * 2;
    }

    // ldmatrix lane offsets
    const uint32_t aL = (uint32_t)((lane & 15) * PAD + (lane >> 4) * 8) * 2;
    const uint32_t bL = (uint32_t)(((lane & 7) + ((lane >> 4) << 3)) * PAD
                                   + ((lane >> 3) & 1) * 8) * 2;
    const uint32_t aWm = (uint32_t)(wm * 32 * PAD) * 2;
    const uint32_t bWn = (uint32_t)(wn * 32 * PAD) * 2;

    auto issue = [&](int st, int buf) {
        const int kc = st << 6;         // 64 halfs per stage
        const uint32_t s0 = sbase + buf * STAGE_B;
        #pragma unroll
        for (int i = 0; i < 4; i++)
            cpa16(s0 + aSmv[i], A + aGv[i] + kc, aszv[i]);
        #pragma unroll
        for (int i = 0; i < 2; i++)
            cpa16(s0 + A_TILE_B + bSmv[i], B2 + bGv[i] + kc, 16);
        asm volatile("cp.async.commit_group;" ::: "memory");
    };

    issue(0, 0);
    if (nst > 1) issue(1, 1);
    int buf = 0;
    #pragma unroll 1
    for (int st = 0; st < nst; st++) {
        if (st + 1 < nst)
            asm volatile("cp.async.wait_group 1;" ::: "memory");
        else
            asm volatile("cp.async.wait_group 0;" ::: "memory");
        __syncthreads();
        const uint32_t s0 = sbase + buf * STAGE_B;
        #pragma unroll
        for (int ks = 0; ks < 4; ks++) {
            uint32_t aH[2][4], bH[2][4];
            #pragma unroll
            for (int mi = 0; mi < 2; mi++)
                ldsm4(aH[mi], s0 + aWm + aL + (uint32_t)(mi * 16 * PAD + ks * 16) * 2);
            #pragma unroll
            for (int njp = 0; njp < 2; njp++)
                ldsm4(bH[njp], s0 + A_TILE_B + bWn + bL + (uint32_t)(njp * 16 * PAD + ks * 16) * 2);
            #pragma unroll
            for (int mi = 0; mi < 2; mi++)
                #pragma unroll
                for (int nj = 0; nj < 4; nj++)
                    mma16816(accP[mi][nj], aH[mi], &bH[nj >> 1][(nj & 1) * 2]);
        }
        // issue stage st+2 into the buffer just consumed — AFTER all warps
        // have finished reading it (barrier closes the round-16 race).
        if (st + 2 < nst) {
            __syncthreads();
            issue(st + 2, buf);
        }
        buf ^= 1;
    }

    if (mode != 1) {
        #pragma unroll
        for (int mi = 0; mi < 2; mi++)
            #pragma unroll
            for (int nj = 0; nj < 4; nj++) {
                const int c0 = n0 + wn * 32 + nj * 8 + (lane & 3) * 2;
                const int rr = m0 + wm * 32 + mi * 16 + (lane >> 2);
                const float2 bs = make_float2(bias[c0], bias[c0 + 1]);
                float v0 = accP[mi][nj][0] + bs.x;
                float v1 = accP[mi][nj][1] + bs.y;
                float v2 = accP[mi][nj][2] + bs.x;
                float v3 = accP[mi][nj][3] + bs.y;
                if (mode == 0) {
                    if (rr < NN)     *(float2*)(XpOut + (size_t)rr * 2048 + c0) = make_float2(v0, v1);
                    if (rr + 8 < NN) *(float2*)(XpOut + (size_t)(rr + 8) * 2048 + c0) = make_float2(v2, v3);
                } else {  // mode 2: fp16 write
                    if (rr < NN)
                        *(__half2*)(hout + (size_t)rr * hstride + hoff + c0) =
                            __halves2half2(__float2half_rn(v0), __float2half_rn(v1));
                    if (rr + 8 < NN)
                        *(__half2*)(hout + (size_t)(rr + 8) * hstride + hoff + c0) =
                            __halves2half2(__float2half_rn(v2), __float2half_rn(v3));
                }
            }
    } else {
        #pragma unroll
        for (int mi = 0; mi < 2; mi++)
            #pragma unroll
            for (int nj = 0; nj < 4; nj++) {
                float v0 = accP[mi][nj][0];
                float v1 = accP[mi][nj][1];
                float v2 = accP[mi][nj][2];
                float v3 = accP[mi][nj][3];
                const float p0 = __shfl_xor_sync(0xffffffffu, v0, 1);
                const float p1 = __shfl_xor_sync(0xffffffffu, v1, 1);
                const float p2 = __shfl_xor_sync(0xffffffffu, v2, 1);
                const float p3 = __shfl_xor_sync(0xffffffffu, v3, 1);
                const int q = lane & 1;
                const int rl = wm * 32 + mi * 16 + (lane >> 2) + (q << 3);
                const int rowU = m0 + rl;
                const int hc = ((n0 + wn * 32 + nj * 8) >> 2) + ((lane & 3) >> 1);
                if (rowU < NN) {
                    float gi, gf, gg, go;
                    if (!q) { gi = v0; gf = v1; gg = p0; go = p1; }
                    else    { gi = p2; gf = p3; gg = v2; go = v3; }
                    const int s = sSrc[rl];
                    const float4 xv = *(const float4*)(XpIn + (size_t)s * 2048 + 4 * hc);
                    gi += xv.x; gf += xv.y; gg += xv.z; go += xv.w;
                    const size_t ci = (size_t)rowU * FF + hc;
                    const float cn = sig_(gf) * cbuf[ci] + sig_(gi) * tanh_(gg);
                    cbuf[ci] = cn;
                    const float hv = sig_(go) * tanh_(cn);
                    if (h32out) h32out[ci] = hv;
                    if (hout) hout[(size_t)rowU * hstride + hoff + hc] = __float2half_rn(hv);
                }
            }
    }
}

// ---------------------------------------------------------------------------
// conv_w: W fp32 [2048,512] (rows gate*512+hc) -> fp16 [2048][512] interleaved
// row jp = 4*hc + gate; bsum[jp] = b1 + b2
// ---------------------------------------------------------------------------
__global__ void __launch_bounds__(256) conv_w_kernel(
    const float* __restrict__ W, const float* __restrict__ b1, const float* __restrict__ b2,
    __half* __restrict__ W2, float* __restrict__ bsum)
{
    const int idx = blockIdx.x * 256 + threadIdx.x;
    if (idx >= 2048 * 512) return;
    const int jp = idx >> 9, k = idx & 511;
    const int orig = (jp & 3) * 512 + (jp >> 2);
    W2[(size_t)jp * 512 + k] = __float2half_rn(W[(size_t)orig * 512 + k]);
    if (k == 0 && bsum) bsum[jp] = b1[orig] + b2[orig];
}

// conv_w_sage: WbS[512][1024]: row j, k<512 -> Wself[k,j]; k>=512 -> Wneigh[k-512,j]
__global__ void __launch_bounds__(256) conv_w_sage_kernel(
    const float* __restrict__ Ws, const float* __restrict__ Wn,
    __half* __restrict__ W2)
{
    const int idx = blockIdx.x * 256 + threadIdx.x;
    if (idx >= 512 * 1024) return;
    const int j = idx >> 10, k = idx & 1023;
    const float w = (k < 512) ? Ws[(size_t)k * 512 + j] : Wn[(size_t)(k - 512) * 512 + j];
    W2[(size_t)j * 1024 + k] = __float2half_rn(w);
}

// conv_a: x fp32 -> fp16 into sageA cols 0..511 (stride 1024)
__global__ void __launch_bounds__(256) conv_a_kernel(
    const float* __restrict__ X, __half* __restrict__ A2)
{
    const int idx = blockIdx.x * 256 + threadIdx.x;
    if (idx >= NN * 512) return;
    const int n = idx >> 9, k = idx & 511;
    A2[(size_t)n * 1024 + k] = __float2half_rn(X[idx]);
}

// first LSTM step (t=0): gates = Xp[src[:,0]]; write c + h fp16
__global__ void __launch_bounds__(256) lstm_first_kernel(
    const float* __restrict__ Xp, const int* __restrict__ src,
    float* __restrict__ c, __half* __restrict__ hout)
{
    const int idx = blockIdx.x * 256 + threadIdx.x;
    if (idx >= NN * 512) return;
    const int n = idx >> 9, hc = idx & 511;
    const int s = src[n * DEG];
    const float4 xv = *(const float4*)(Xp + (size_t)s * 2048 + 4 * hc);
    const float cn = sig_(xv.x) * tanh_(xv.z);
    c[idx] = cn;
    hout[idx] = __float2half_rn(sig_(xv.w) * tanh_(cn));
}

// ---------------------------------------------------------------------------
extern "C" void kernel_launch(void* const* d_in, const int* in_sizes, int n_in,
                              void* d_out, int out_size)
{
    const float* x      = (const float*)d_in[0];
    const int*   src    = (const int*)  d_in[1];
    const float* Wih1   = (const float*)d_in[2];
    const float* Whh1   = (const float*)d_in[3];
    const float* bih1   = (const float*)d_in[4];
    const float* bhh1   = (const float*)d_in[5];
    const float* Wself  = (const float*)d_in[6];
    const float* Wneigh = (const float*)d_in[7];
    const float* b      = (const float*)d_in[8];
    const float* Wih2   = (const float*)d_in[9];
    const float* Whh2   = (const float*)d_in[10];
    const float* bih2   = (const float*)d_in[11];
    const float* bhh2   = (const float*)d_in[12];
    float* out = (float*)d_out;

    float *Xp, *bsum1, *bsum2, *c;
    __half *sageA, *hA, *hB, *hs16, *Wih1b, *Whh1b, *Wih2b, *Whh2b, *WbS;
    cudaGetSymbolAddress((void**)&Xp,    g_Xp);
    cudaGetSymbolAddress((void**)&sageA, g_sageA);
    cudaGetSymbolAddress((void**)&hA,    g_hA);
    cudaGetSymbolAddress((void**)&hB,    g_hB);
    cudaGetSymbolAddress((void**)&hs16,  g_hs16);
    cudaGetSymbolAddress((void**)&Wih1b, g_Wih1b);
    cudaGetSymbolAddress((void**)&Whh1b, g_Whh1b);
    cudaGetSymbolAddress((void**)&Wih2b, g_Wih2b);
    cudaGetSymbolAddress((void**)&Whh2b, g_Whh2b);
    cudaGetSymbolAddress((void**)&WbS,   g_WbS);
    cudaGetSymbolAddress((void**)&bsum1, g_bsum1);
    cudaGetSymbolAddress((void**)&bsum2, g_bsum2);
    cudaGetSymbolAddress((void**)&c,     g_c);

    cudaFuncSetAttribute(gemm_f16_kernel,
                         cudaFuncAttributeMaxDynamicSharedMemorySize, SMEMB);

    const dim3 gMain((NN + 127) / 128, 32);   // 2048 output cols / 64
    const dim3 gSage((NN + 127) / 128, 8);    // 512 output cols / 64
    const int  gElem  = (NN * 512) / 256;
    const int  gConvW = (2048 * 512) / 256;
    const int  gConvS = (512 * 1024) / 256;

    // Launch order: index 5 (ncu -s 5 -c 1) is the first mode-1 LSTM GEMM step.
    conv_a_kernel<<<gElem, 256>>>(x, sageA);                                // #0
    conv_w_kernel<<<gConvW, 256>>>(Wih1, bih1, bhh1, Wih1b, bsum1);         // #1
    conv_w_kernel<<<gConvW, 256>>>(Whh1, nullptr, nullptr, Whh1b, nullptr); // #2
    gemm_f16_kernel<<<gMain, 256, SMEMB>>>(sageA, 1024, Wih1b, 512, 0,
        bsum1, Xp, nullptr, nullptr, 0, nullptr, nullptr, 0, 0, nullptr);   // #3
    lstm_first_kernel<<<gElem, 256>>>(Xp, src, c, hB);                      // #4
    for (int t = 1; t <= 30; t++) {                                         // #5 = t=1
        __half* hin  = (t & 1) ? hB : hA;
        __half* hout = (t & 1) ? hA : hB;
        gemm_f16_kernel<<<gMain, 256, SMEMB>>>(hin, 512, Whh1b, 512, 1,
            nullptr, nullptr, Xp, src, t, c, hout, 512, 0, nullptr);
    }
    gemm_f16_kernel<<<gMain, 256, SMEMB>>>(hB, 512, Whh1b, 512, 1,
        nullptr, nullptr, Xp, src, 31, c, sageA, 1024, 512, nullptr);

    conv_w_sage_kernel<<<gConvS, 256>>>(Wself, Wneigh, WbS);
    gemm_f16_kernel<<<gSage, 256, SMEMB>>>(sageA, 1024, WbS, 1024, 2,
        b, nullptr, nullptr, nullptr, 0, nullptr, hs16, 512, 0, nullptr);

    conv_w_kernel<<<gConvW, 256>>>(Wih2, bih2, bhh2, Wih2b, bsum2);
    conv_w_kernel<<<gConvW, 256>>>(Whh2, nullptr, nullptr, Whh2b, nullptr);
    gemm_f16_kernel<<<gMain, 256, SMEMB>>>(hs16, 512, Wih2b, 512, 0,
        bsum2, Xp, nullptr, nullptr, 0, nullptr, nullptr, 0, 0, nullptr);
    lstm_first_kernel<<<gElem, 256>>>(Xp, src, c, hB);
    for (int t = 1; t <= 30; t++) {
        __half* hin  = (t & 1) ? hB : hA;
        __half* hout = (t & 1) ? hA : hB;
        gemm_f16_kernel<<<gMain, 256, SMEMB>>>(hin, 512, Whh2b, 512, 1,
            nullptr, nullptr, Xp, src, t, c, hout, 512, 0, nullptr);
    }
    gemm_f16_kernel<<<gMain, 256, SMEMB>>>(hB, 512, Whh2b, 512, 1,
        nullptr, nullptr, Xp, src, 31, c, nullptr, 0, 0, out);
}